// round 15
// baseline (speedup 1.0000x reference)
#include <cuda_runtime.h>
#include <cuda_bf16.h>
#include <math.h>
#include <stdint.h>

#define NROWS 500000
#define DIN   256
#define DHID  128
#define NHEAD 4
#define HBLK  32
#define DOUT  4
#define TM    128
#define NCHUNK 16            // 16 orig-k per chunk

// smem offsets from 1024-aligned base
#define OFF_IDX 0            // 128 int
#define OFF_W2  512          // 128 float
#define OFF_B   1024         // 512 cat-rows x 32 bf16 (64 B/row) = 32 KB
#define OFF_A0  33792        // A bufs: 2 x (8 warps x 1 KB) = 16 KB
#define SMEM_REQ (50176 + 1024)

// ---------------- scratch ----------------
__device__ int g_cnt[NHEAD];
__device__ unsigned int g_done;
__device__ int g_idx[NHEAD][NROWS];

// ---------------- kernel 1: bucket rows by head ----------------
__global__ void scatter_kernel(const int* __restrict__ heads, int n) {
    __shared__ int s_cnt[NHEAD];
    __shared__ int s_base[NHEAD];
    int t = blockIdx.x * blockDim.x + threadIdx.x;
    if (threadIdx.x < NHEAD) s_cnt[threadIdx.x] = 0;
    __syncthreads();
    int h = 0, rank = 0;
    bool valid = (t < n);
    if (valid) {
        h = heads[t];
        rank = atomicAdd(&s_cnt[h], 1);
    }
    __syncthreads();
    if (threadIdx.x < NHEAD)
        s_base[threadIdx.x] = atomicAdd(&g_cnt[threadIdx.x], s_cnt[threadIdx.x]);
    __syncthreads();
    if (valid) g_idx[h][s_base[h] + rank] = t;
}

// ---------------- PTX helpers ----------------
__device__ __forceinline__ uint32_t smem_u32(const void* p) {
    uint32_t a;
    asm("{ .reg .u64 t; cvta.to.shared.u64 t, %1; cvt.u32.u64 %0, t; }"
        : "=r"(a) : "l"(p));
    return a;
}
__device__ __forceinline__ void ldm_x4(uint32_t* r, uint32_t addr) {
    asm volatile("ldmatrix.sync.aligned.m8n8.x4.shared.b16 {%0,%1,%2,%3}, [%4];"
                 : "=r"(r[0]), "=r"(r[1]), "=r"(r[2]), "=r"(r[3]) : "r"(addr));
}
__device__ __forceinline__ void ldm_x4_t(uint32_t* r, uint32_t addr) {
    asm volatile("ldmatrix.sync.aligned.m8n8.x4.trans.shared.b16 {%0,%1,%2,%3}, [%4];"
                 : "=r"(r[0]), "=r"(r[1]), "=r"(r[2]), "=r"(r[3]) : "r"(addr));
}
__device__ __forceinline__ void mma_bf16(float* d, const uint32_t* a, const uint32_t* b) {
    asm volatile("mma.sync.aligned.m16n8k16.row.col.f32.bf16.bf16.f32 "
                 "{%0,%1,%2,%3}, {%4,%5,%6,%7}, {%8,%9}, {%0,%1,%2,%3};"
                 : "+f"(d[0]), "+f"(d[1]), "+f"(d[2]), "+f"(d[3])
                 : "r"(a[0]), "r"(a[1]), "r"(a[2]), "r"(a[3]), "r"(b[0]), "r"(b[1]));
}
__device__ __forceinline__ uint32_t hswap(uint32_t v) {
    uint32_t r;
    asm("prmt.b32 %0, %1, %1, 0x1032;" : "=r"(r) : "r"(v));
    return r;
}
__device__ __forceinline__ void splitpack2(float f0, float f1,
                                           uint32_t& w0, uint32_t& w1) {
    uint32_t h, l;
    asm("cvt.rn.bf16x2.f32 %0, %1, %2;" : "=r"(h) : "f"(f1), "f"(f0));
    float f0h = __uint_as_float(h << 16);
    float f1h = __uint_as_float(h & 0xffff0000u);
    asm("cvt.rn.bf16x2.f32 %0, %1, %2;" : "=r"(l) : "f"(f1 - f1h), "f"(f0 - f0h));
    asm("prmt.b32 %0, %1, %2, 0x5410;" : "=r"(w0) : "r"(h), "r"(l));
    asm("prmt.b32 %0, %1, %2, 0x7632;" : "=r"(w1) : "r"(h), "r"(l));
}

// ---------------- kernel 2: 8-warp CTA, 4 CTA/SM, warp-independent HMMA ----
// 256 threads; each warp owns 16 rows end-to-end. Single-stage register
// staging (16 regs) so the whole kernel fits in 64 regs -> 4 CTAs/SM.
__global__ void __launch_bounds__(256, 4)
mma_kernel(const float* __restrict__ x,
           const float* __restrict__ W1,
           const float* __restrict__ W2,
           float* __restrict__ out) {
    extern __shared__ char smraw[];
    __shared__ int s_c[NHEAD];

    const int tid  = threadIdx.x;
    const int lane = tid & 31;
    const int warp = tid >> 5;           // 0..7

    // ---- read counts, publish, ticket-zero for next graph replay ----
    if (tid == 0) {
        s_c[0] = g_cnt[0]; s_c[1] = g_cnt[1];
        s_c[2] = g_cnt[2]; s_c[3] = g_cnt[3];
    }
    __syncthreads();
    if (tid == 0) {
        unsigned int old = atomicAdd(&g_done, 1u);
        if (old % gridDim.x == gridDim.x - 1) {
            g_cnt[0] = 0; g_cnt[1] = 0; g_cnt[2] = 0; g_cnt[3] = 0;
        }
    }

    // ---- resolve (head, tile) ----
    const int c0 = s_c[0], c1 = s_c[1], c2 = s_c[2], c3 = s_c[3];
    const int t0 = (c0 + TM - 1) >> 7, t1 = (c1 + TM - 1) >> 7,
              t2 = (c2 + TM - 1) >> 7, t3 = (c3 + TM - 1) >> 7;
    int b = blockIdx.x;
    int hd, cnt;
    if (b < t0)              { hd = 0; cnt = c0; }
    else if ((b -= t0) < t1) { hd = 1; cnt = c1; }
    else if ((b -= t1) < t2) { hd = 2; cnt = c2; }
    else if ((b -= t2) < t3) { hd = 3; cnt = c3; }
    else return;
    const int start = b << 7;

    const uint32_t raw  = smem_u32(smraw);
    const uint32_t base = (raw + 1023u) & ~1023u;
    char* smc = smraw + (base - raw);

    // ---- prologue: row indices, scaled W2 (first 128 threads), B tile ----
    if (tid < TM) {
        int rr = start + tid;
        if (rr >= cnt) rr = cnt - 1;
        *(int*)(smc + OFF_IDX + tid * 4) = g_idx[hd][rr];
        int j = tid >> 2, d = tid & 3;
        *(float*)(smc + OFF_W2 + tid * 4) =
            W2[(hd * HBLK + j) * DOUT + d] * 0.08838834764831845f;
    }
    {
        const int n  = tid & 31;
        const int k0 = tid >> 5;                  // 0..7
        const uint32_t nc = (uint32_t)(n >> 3);
        const float* wp = W1 + hd * HBLK + n;
        #pragma unroll 4
        for (int i = 0; i < 32; ++i) {
            int k = k0 + 8 * i;
            float w = wp[k * DHID] * 0.0625f;     // fold 1/sqrt(256)
            __nv_bfloat16 hb = __float2bfloat16(w);
            float hf = __bfloat162float(hb);
            __nv_bfloat16 lb = __float2bfloat16(w - hf);
            uint32_t off = OFF_B + (uint32_t)(2 * k) * 64u +
                           (((uint32_t)nc ^ (uint32_t)(k & 3)) << 4) +
                           (uint32_t)(n & 7) * 2u;
            *(__nv_bfloat16*)(smc + off)      = hb;
            *(__nv_bfloat16*)(smc + off + 64) = lb;
        }
    }
    __syncthreads();   // only CTA barrier: B tile + IDX visible to all warps

    // ---- gather lane constants (warp owns rows warp*16 + rq + 8i) ----
    const int s3 = lane & 3;                      // 16B slot within 64B chunk
    const int rq = lane >> 2;                     // 0..7
    const uint32_t wbuf = (uint32_t)warp * 1024u; // warp-private buf offset
    uint32_t rofs[2];
    uint32_t rbyte[2];
    #pragma unroll
    for (int i = 0; i < 2; ++i) {
        int r = warp * 16 + rq + 8 * i;
        rofs[i]  = *(const uint32_t*)(smc + OFF_IDX + r * 4) * 1024u
                   + (uint32_t)(s3 * 16);
        rbyte[i] = (uint32_t)(rq + 8 * i) * 64u +
                   ((uint32_t)(s3 ^ ((rq >> 1) & 3)) << 4);
    }
    const char* xB = (const char*)x;

    // ---- MMA lane constants ----
    const int g     = lane >> 3;
    const int l7    = lane & 7;
    const int ghalf = g >> 1;
    const uint32_t aswz = (uint32_t)((l7 >> 1) & 3);
    const int klo   = (g & 1) * 8 + l7;
    const uint32_t abase = base + OFF_A0 + wbuf +
                           (uint32_t)((g & 1) * 8 + l7) * 64u;

    float acc[4][4];
    #pragma unroll
    for (int nt = 0; nt < 4; ++nt)
        #pragma unroll
        for (int j = 0; j < 4; ++j) acc[nt][j] = 0.f;

    // ---- prologue: stage chunk 0 (single-stage staging: 16 regs) ----
    float4 st[2];
    #pragma unroll
    for (int i = 0; i < 2; ++i) st[i] = *(const float4*)(xB + rofs[i]);

    #pragma unroll 1
    for (int ch = 0; ch < NCHUNK; ++ch) {
        const uint32_t bufo = (uint32_t)(ch & 1) * 8192u;

        // ---- convert + STS current chunk, then reload st in place ----
        #pragma unroll
        for (int i = 0; i < 2; ++i) {
            uint4 wv;
            splitpack2(st[i].x, st[i].y, wv.x, wv.y);
            splitpack2(st[i].z, st[i].w, wv.z, wv.w);
            *(uint4*)(smc + OFF_A0 + bufo + wbuf + rbyte[i]) = wv;
        }
        if (ch + 1 < NCHUNK) {
            uint32_t add = (uint32_t)(ch + 1) * 64u;
            #pragma unroll
            for (int i = 0; i < 2; ++i)
                st[i] = *(const float4*)(xB + rofs[i] + add);
        }
        __syncwarp();    // order STS -> LDSM within the warp only

        // ---- MMA on warp-private buf: 2 k-steps ----
        #pragma unroll
        for (int ksl = 0; ksl < 2; ++ksl) {
            uint32_t afr[4], asw[4], bfr[2][4];
            {
                int row = ch * 32 + ksl * 16 + klo;
                uint32_t bsw = (uint32_t)((row >> 1) & 3);
                #pragma unroll
                for (int np = 0; np < 2; ++np) {
                    uint32_t nc2 = (uint32_t)(np * 2 + ghalf);
                    ldm_x4_t(bfr[np], base + OFF_B + (uint32_t)row * 64u +
                                      ((nc2 ^ bsw) << 4));
                }
            }
            const uint32_t cc = (uint32_t)(2 * ksl + ghalf);
            ldm_x4(afr, abase + bufo + ((cc ^ aswz) << 4));
            #pragma unroll
            for (int j = 0; j < 4; ++j) asw[j] = hswap(afr[j]);
            #pragma unroll
            for (int np = 0; np < 2; ++np) {
                mma_bf16(acc[np * 2 + 0], afr, bfr[np] + 0);
                mma_bf16(acc[np * 2 + 1], afr, bfr[np] + 2);
                mma_bf16(acc[np * 2 + 0], asw, bfr[np] + 0);
                mma_bf16(acc[np * 2 + 1], asw, bfr[np] + 2);
            }
        }
    }

    // ---- epilogue: silu + W2, quad reduction, scattered store ----
    const int q  = lane & 3;
    const int r0 = lane >> 2;

    float4 osum[2];
    osum[0] = make_float4(0.f, 0.f, 0.f, 0.f);
    osum[1] = make_float4(0.f, 0.f, 0.f, 0.f);

    #pragma unroll
    for (int nt = 0; nt < 4; ++nt) {
        float4 wcj[2];
        #pragma unroll
        for (int j = 0; j < 2; ++j)
            wcj[j] = *(const float4*)(smc + OFF_W2 + (nt * 8 + q * 2 + j) * 16);
        #pragma unroll
        for (int idx = 0; idx < 4; ++idx) {
            int hh = idx >> 1, j = idx & 1;
            float hv = acc[nt][idx];
            float sv = hv / (1.f + __expf(-hv));
            osum[hh].x += sv * wcj[j].x;
            osum[hh].y += sv * wcj[j].y;
            osum[hh].z += sv * wcj[j].z;
            osum[hh].w += sv * wcj[j].w;
        }
    }

    #pragma unroll
    for (int mbit = 1; mbit <= 2; mbit <<= 1)
        #pragma unroll
        for (int hh = 0; hh < 2; ++hh) {
            osum[hh].x += __shfl_xor_sync(0xffffffffu, osum[hh].x, mbit);
            osum[hh].y += __shfl_xor_sync(0xffffffffu, osum[hh].y, mbit);
            osum[hh].z += __shfl_xor_sync(0xffffffffu, osum[hh].z, mbit);
            osum[hh].w += __shfl_xor_sync(0xffffffffu, osum[hh].w, mbit);
        }

    if (q == 0) {
        #pragma unroll
        for (int hh = 0; hh < 2; ++hh) {
            int rl = warp * 16 + hh * 8 + r0;
            if (start + rl < cnt) {
                int ridx = *(const int*)(smc + OFF_IDX + rl * 4);
                *(float4*)(out + (size_t)ridx * DOUT) = osum[hh];
            }
        }
    }
}

// ---------------- launch ----------------
extern "C" void kernel_launch(void* const* d_in, const int* in_sizes, int n_in,
                              void* d_out, int out_size) {
    const float* x     = (const float*)d_in[0];
    const float* W1    = (const float*)d_in[1];
    const float* W2    = (const float*)d_in[2];
    const int*   heads = (const int*)d_in[3];
    int n = in_sizes[3];

    static int attr_done = 0;
    if (!attr_done) {
        cudaFuncSetAttribute(mma_kernel,
                             cudaFuncAttributeMaxDynamicSharedMemorySize, SMEM_REQ);
        attr_done = 1;
    }

    scatter_kernel<<<(n + 255) / 256, 256>>>(heads, n);

    int nt = (n + TM - 1) / TM + (NHEAD - 1);
    mma_kernel<<<nt, 256, SMEM_REQ>>>(x, W1, W2, (float*)d_out);
}

// round 17
// speedup vs baseline: 1.0755x; 1.0755x over previous
#include <cuda_runtime.h>
#include <cuda_bf16.h>
#include <math.h>
#include <stdint.h>

#define NROWS 500000
#define DIN   256
#define DHID  128
#define NHEAD 4
#define HBLK  32
#define DOUT  4
#define TM    128
#define NCHUNK 8             // 32 orig-k (128 B) per chunk

// smem offsets from 1024-aligned base
#define OFF_IDX 0            // 128 int
#define OFF_W2  512          // 128 float
#define OFF_B   1024         // 512 cat-rows x 32 bf16 (64 B/row) = 32 KB
#define OFF_A0  33792        // A bufs: 2 x (8 warps x 2 KB) = 32 KB
#define SMEM_REQ (66560 + 1024)

// ---------------- scratch ----------------
__device__ int g_cnt[NHEAD];
__device__ unsigned int g_done;
__device__ int g_idx[NHEAD][NROWS];

// ---------------- kernel 1: bucket rows by head ----------------
__global__ void scatter_kernel(const int* __restrict__ heads, int n) {
    __shared__ int s_cnt[NHEAD];
    __shared__ int s_base[NHEAD];
    int t = blockIdx.x * blockDim.x + threadIdx.x;
    if (threadIdx.x < NHEAD) s_cnt[threadIdx.x] = 0;
    __syncthreads();
    int h = 0, rank = 0;
    bool valid = (t < n);
    if (valid) {
        h = heads[t];
        rank = atomicAdd(&s_cnt[h], 1);
    }
    __syncthreads();
    if (threadIdx.x < NHEAD)
        s_base[threadIdx.x] = atomicAdd(&g_cnt[threadIdx.x], s_cnt[threadIdx.x]);
    __syncthreads();
    if (valid) g_idx[h][s_base[h] + rank] = t;
}

// ---------------- PTX helpers ----------------
__device__ __forceinline__ uint32_t smem_u32(const void* p) {
    uint32_t a;
    asm("{ .reg .u64 t; cvta.to.shared.u64 t, %1; cvt.u32.u64 %0, t; }"
        : "=r"(a) : "l"(p));
    return a;
}
__device__ __forceinline__ void ldm_x4(uint32_t* r, uint32_t addr) {
    asm volatile("ldmatrix.sync.aligned.m8n8.x4.shared.b16 {%0,%1,%2,%3}, [%4];"
                 : "=r"(r[0]), "=r"(r[1]), "=r"(r[2]), "=r"(r[3]) : "r"(addr));
}
__device__ __forceinline__ void ldm_x4_t(uint32_t* r, uint32_t addr) {
    asm volatile("ldmatrix.sync.aligned.m8n8.x4.trans.shared.b16 {%0,%1,%2,%3}, [%4];"
                 : "=r"(r[0]), "=r"(r[1]), "=r"(r[2]), "=r"(r[3]) : "r"(addr));
}
__device__ __forceinline__ void mma_bf16(float* d, const uint32_t* a, const uint32_t* b) {
    asm volatile("mma.sync.aligned.m16n8k16.row.col.f32.bf16.bf16.f32 "
                 "{%0,%1,%2,%3}, {%4,%5,%6,%7}, {%8,%9}, {%0,%1,%2,%3};"
                 : "+f"(d[0]), "+f"(d[1]), "+f"(d[2]), "+f"(d[3])
                 : "r"(a[0]), "r"(a[1]), "r"(a[2]), "r"(a[3]), "r"(b[0]), "r"(b[1]));
}
__device__ __forceinline__ uint32_t hswap(uint32_t v) {
    uint32_t r;
    asm("prmt.b32 %0, %1, %1, 0x1032;" : "=r"(r) : "r"(v));
    return r;
}
__device__ __forceinline__ void splitpack2(float f0, float f1,
                                           uint32_t& w0, uint32_t& w1) {
    uint32_t h, l;
    asm("cvt.rn.bf16x2.f32 %0, %1, %2;" : "=r"(h) : "f"(f1), "f"(f0));
    float f0h = __uint_as_float(h << 16);
    float f1h = __uint_as_float(h & 0xffff0000u);
    asm("cvt.rn.bf16x2.f32 %0, %1, %2;" : "=r"(l) : "f"(f1 - f1h), "f"(f0 - f0h));
    asm("prmt.b32 %0, %1, %2, 0x5410;" : "=r"(w0) : "r"(h), "r"(l));
    asm("prmt.b32 %0, %1, %2, 0x7632;" : "=r"(w1) : "r"(h), "r"(l));
}

// ---------------- kernel 2: 8-warp CTA, 128B-chunk warp-independent HMMA ----
// Each warp owns 16 rows; gathers 128 B/row/chunk (4-line LDGs) into a
// warp-private 2 KB double buffer; A-row = 128 B so swizzle = slot ^ (row&7).
__global__ void __launch_bounds__(256, 3)
mma_kernel(const float* __restrict__ x,
           const float* __restrict__ W1,
           const float* __restrict__ W2,
           float* __restrict__ out) {
    extern __shared__ char smraw[];
    __shared__ int s_c[NHEAD];

    const int tid  = threadIdx.x;
    const int lane = tid & 31;
    const int warp = tid >> 5;           // 0..7

    // ---- read counts, publish, ticket-zero for next graph replay ----
    if (tid == 0) {
        s_c[0] = g_cnt[0]; s_c[1] = g_cnt[1];
        s_c[2] = g_cnt[2]; s_c[3] = g_cnt[3];
    }
    __syncthreads();
    if (tid == 0) {
        unsigned int old = atomicAdd(&g_done, 1u);
        if (old % gridDim.x == gridDim.x - 1) {
            g_cnt[0] = 0; g_cnt[1] = 0; g_cnt[2] = 0; g_cnt[3] = 0;
        }
    }

    // ---- resolve (head, tile) ----
    const int c0 = s_c[0], c1 = s_c[1], c2 = s_c[2], c3 = s_c[3];
    const int t0 = (c0 + TM - 1) >> 7, t1 = (c1 + TM - 1) >> 7,
              t2 = (c2 + TM - 1) >> 7, t3 = (c3 + TM - 1) >> 7;
    int b = blockIdx.x;
    int hd, cnt;
    if (b < t0)              { hd = 0; cnt = c0; }
    else if ((b -= t0) < t1) { hd = 1; cnt = c1; }
    else if ((b -= t1) < t2) { hd = 2; cnt = c2; }
    else if ((b -= t2) < t3) { hd = 3; cnt = c3; }
    else return;
    const int start = b << 7;

    const uint32_t raw  = smem_u32(smraw);
    const uint32_t base = (raw + 1023u) & ~1023u;
    char* smc = smraw + (base - raw);

    // ---- prologue: row indices, scaled W2 (first 128 threads), B tile ----
    if (tid < TM) {
        int rr = start + tid;
        if (rr >= cnt) rr = cnt - 1;
        *(int*)(smc + OFF_IDX + tid * 4) = g_idx[hd][rr];
        int j = tid >> 2, d = tid & 3;
        *(float*)(smc + OFF_W2 + tid * 4) =
            W2[(hd * HBLK + j) * DOUT + d] * 0.08838834764831845f;
    }
    {
        const int n  = tid & 31;
        const int k0 = tid >> 5;                  // 0..7
        const uint32_t nc = (uint32_t)(n >> 3);
        const float* wp = W1 + hd * HBLK + n;
        #pragma unroll 4
        for (int i = 0; i < 32; ++i) {
            int k = k0 + 8 * i;
            float w = wp[k * DHID] * 0.0625f;     // fold 1/sqrt(256)
            __nv_bfloat16 hb = __float2bfloat16(w);
            float hf = __bfloat162float(hb);
            __nv_bfloat16 lb = __float2bfloat16(w - hf);
            uint32_t off = OFF_B + (uint32_t)(2 * k) * 64u +
                           (((uint32_t)nc ^ (uint32_t)(k & 3)) << 4) +
                           (uint32_t)(n & 7) * 2u;
            *(__nv_bfloat16*)(smc + off)      = hb;
            *(__nv_bfloat16*)(smc + off + 64) = lb;
        }
    }
    __syncthreads();   // only CTA barrier: B tile + IDX visible to all warps

    // ---- gather lane constants: lane = 4 rows x 8 slots per LDG ----
    const int s7 = lane & 7;                      // 16B slot within 128B chunk
    const int rl = lane >> 3;                     // 0..3 row-in-group
    const uint32_t wbuf = (uint32_t)warp * 2048u; // warp-private buf offset
    uint32_t rofs[4];
    uint32_t rbyte[4];
    #pragma unroll
    for (int i = 0; i < 4; ++i) {
        int r = warp * 16 + rl + 4 * i;           // warp-local row rl+4i
        rofs[i]  = *(const uint32_t*)(smc + OFF_IDX + r * 4) * 1024u
                   + (uint32_t)(s7 * 16);
        int rloc = rl + 4 * i;
        rbyte[i] = (uint32_t)rloc * 128u +
                   ((uint32_t)(s7 ^ (rloc & 7)) << 4);
    }
    const char* xB = (const char*)x;

    // ---- MMA lane constants ----
    const int g     = lane >> 3;
    const int l7    = lane & 7;
    const int ghalf = g >> 1;
    const int klo   = (g & 1) * 8 + l7;
    const uint32_t abase = base + OFF_A0 + wbuf +
                           (uint32_t)((g & 1) * 8 + l7) * 128u;

    float acc[4][4];
    #pragma unroll
    for (int nt = 0; nt < 4; ++nt)
        #pragma unroll
        for (int j = 0; j < 4; ++j) acc[nt][j] = 0.f;

    // ---- prologue: stage chunk 0 (16 regs) ----
    float4 st[4];
    #pragma unroll
    for (int i = 0; i < 4; ++i) st[i] = *(const float4*)(xB + rofs[i]);

    #pragma unroll 1
    for (int ch = 0; ch < NCHUNK; ++ch) {
        const uint32_t bufo = (uint32_t)(ch & 1) * 16384u;

        // ---- convert + STS current chunk, then reload st in place ----
        #pragma unroll
        for (int i = 0; i < 4; ++i) {
            uint4 wv;
            splitpack2(st[i].x, st[i].y, wv.x, wv.y);
            splitpack2(st[i].z, st[i].w, wv.z, wv.w);
            *(uint4*)(smc + OFF_A0 + bufo + wbuf + rbyte[i]) = wv;
        }
        if (ch + 1 < NCHUNK) {
            uint32_t add = (uint32_t)(ch + 1) * 128u;
            #pragma unroll
            for (int i = 0; i < 4; ++i)
                st[i] = *(const float4*)(xB + rofs[i] + add);
        }
        __syncwarp();    // order STS -> LDSM within the warp only

        // ---- MMA on warp-private buf: 4 k-steps (cat-K 16 each) ----
        #pragma unroll
        for (int ksl = 0; ksl < 4; ++ksl) {
            uint32_t afr[4], asw[4], bfr[2][4];
            {
                int row = ch * 64 + ksl * 16 + klo;
                uint32_t bsw = (uint32_t)((row >> 1) & 3);
                #pragma unroll
                for (int np = 0; np < 2; ++np) {
                    uint32_t nc2 = (uint32_t)(np * 2 + ghalf);
                    ldm_x4_t(bfr[np], base + OFF_B + (uint32_t)row * 64u +
                                      ((nc2 ^ bsw) << 4));
                }
            }
            const uint32_t cc = (uint32_t)(2 * ksl + ghalf);
            ldm_x4(afr, abase + bufo + ((cc ^ (uint32_t)l7) << 4));
            #pragma unroll
            for (int j = 0; j < 4; ++j) asw[j] = hswap(afr[j]);
            #pragma unroll
            for (int np = 0; np < 2; ++np) {
                mma_bf16(acc[np * 2 + 0], afr, bfr[np] + 0);
                mma_bf16(acc[np * 2 + 1], afr, bfr[np] + 2);
                mma_bf16(acc[np * 2 + 0], asw, bfr[np] + 0);
                mma_bf16(acc[np * 2 + 1], asw, bfr[np] + 2);
            }
        }
    }

    // ---- epilogue: silu + W2, quad reduction, scattered store ----
    const int q  = lane & 3;
    const int r0 = lane >> 2;

    float4 osum[2];
    osum[0] = make_float4(0.f, 0.f, 0.f, 0.f);
    osum[1] = make_float4(0.f, 0.f, 0.f, 0.f);

    #pragma unroll
    for (int nt = 0; nt < 4; ++nt) {
        float4 wcj[2];
        #pragma unroll
        for (int j = 0; j < 2; ++j)
            wcj[j] = *(const float4*)(smc + OFF_W2 + (nt * 8 + q * 2 + j) * 16);
        #pragma unroll
        for (int idx = 0; idx < 4; ++idx) {
            int hh = idx >> 1, j = idx & 1;
            float hv = acc[nt][idx];
            float sv = hv / (1.f + __expf(-hv));
            osum[hh].x += sv * wcj[j].x;
            osum[hh].y += sv * wcj[j].y;
            osum[hh].z += sv * wcj[j].z;
            osum[hh].w += sv * wcj[j].w;
        }
    }

    #pragma unroll
    for (int mbit = 1; mbit <= 2; mbit <<= 1)
        #pragma unroll
        for (int hh = 0; hh < 2; ++hh) {
            osum[hh].x += __shfl_xor_sync(0xffffffffu, osum[hh].x, mbit);
            osum[hh].y += __shfl_xor_sync(0xffffffffu, osum[hh].y, mbit);
            osum[hh].z += __shfl_xor_sync(0xffffffffu, osum[hh].z, mbit);
            osum[hh].w += __shfl_xor_sync(0xffffffffu, osum[hh].w, mbit);
        }

    if (q == 0) {
        #pragma unroll
        for (int hh = 0; hh < 2; ++hh) {
            int rlx = warp * 16 + hh * 8 + r0;
            if (start + rlx < cnt) {
                int ridx = *(const int*)(smc + OFF_IDX + rlx * 4);
                *(float4*)(out + (size_t)ridx * DOUT) = osum[hh];
            }
        }
    }
}

// ---------------- launch ----------------
extern "C" void kernel_launch(void* const* d_in, const int* in_sizes, int n_in,
                              void* d_out, int out_size) {
    const float* x     = (const float*)d_in[0];
    const float* W1    = (const float*)d_in[1];
    const float* W2    = (const float*)d_in[2];
    const int*   heads = (const int*)d_in[3];
    int n = in_sizes[3];

    static int attr_done = 0;
    if (!attr_done) {
        cudaFuncSetAttribute(mma_kernel,
                             cudaFuncAttributeMaxDynamicSharedMemorySize, SMEM_REQ);
        attr_done = 1;
    }

    scatter_kernel<<<(n + 255) / 256, 256>>>(heads, n);

    int nt = (n + TM - 1) / TM + (NHEAD - 1);
    mma_kernel<<<nt, 256, SMEM_REQ>>>(x, W1, W2, (float*)d_out);
}